// round 16
// baseline (speedup 1.0000x reference)
#include <cuda_runtime.h>
#include <cuda_bf16.h>

#define BATCH  4
#define SEQ    2048
#define DMODEL 1024
#define NSTATE 16
#define SEG    32                  // segment length
#define NSEGS  (SEQ / SEG)         // 64 segments
#define NCH    (BATCH * DMODEL)    // 4096 channels

typedef unsigned long long ull;

// packed f32x2 helpers (true fp32 lanes — no precision loss)
__device__ __forceinline__ ull pack2(float lo, float hi) {
    ull r; asm("mov.b64 %0, {%1, %2};" : "=l"(r) : "f"(lo), "f"(hi)); return r;
}
__device__ __forceinline__ void fma2(ull& d, ull a, ull b) {
    asm("fma.rn.f32x2 %0, %1, %2, %0;" : "+l"(d) : "l"(a), "l"(b));
}
__device__ __forceinline__ float unpack_add(ull p) {
    float lo, hi; asm("mov.b64 {%0, %1}, %2;" : "=f"(lo), "=f"(hi) : "l"(p));
    return lo + hi;
}
__device__ __forceinline__ void unpack2(float& lo, float& hi, ull p) {
    asm("mov.b64 {%0, %1}, %2;" : "=f"(lo), "=f"(hi) : "l"(p));
}

// ---------------- device scratch (static: no allocation) ----------------
__device__ float4 g_V4[NSEGS * NCH * 4];      // injected state [g][ch][16]  (16.8 MB)
__device__ float4 g_H4[NSEGS * NCH * 4];      // entry states   [g][ch][16]  (16.8 MB)

// ---------------- K1: V = sum_s A^{SEG-1-s} b x_s  (in-block vrev chain + staged x) --
__global__ void __launch_bounds__(256) k1_inject(const float* __restrict__ x,
                                                 const float* __restrict__ A,
                                                 const float* __restrict__ bvec) {
    __shared__ float sA[256];
    __shared__ float sb[NSTATE];
    __shared__ __align__(16) float sv[SEG][NSTATE];   // vrev[s] = A^{SEG-1-s} b
    __shared__ float svc[2][NSTATE];                  // chain double buffer
    __shared__ __align__(16) float sx[SEG][256];      // 32 KB x tile
    const int tid = threadIdx.x;
    sA[tid] = A[tid];
    if (tid < NSTATE) { const float bb = bvec[tid]; sb[tid] = bb; svc[0][tid] = bb; }
    __syncthreads();

    const int bid = blockIdx.x;             // 1024 blocks = 4 dtiles * 4 batch * 64 segs
    const int dt  = bid & 3;
    const int b   = (bid >> 2) & 3;
    const int g   = bid >> 4;

    if (tid < 32) {
        // v-chain (lanes 0-15): v <- A v; overlapped with staging by warps 1-7
        const int m = tid & 15;
        if (tid < NSTATE) sv[SEG - 1][m] = sb[m];
        int cur = 0;
        for (int j = 1; j < SEG; ++j) {
            if (tid < NSTATE) {
                float a = 0.f;
                #pragma unroll
                for (int n = 0; n < NSTATE; ++n) a = fmaf(sA[m * 16 + n], svc[cur][n], a);
                svc[1 - cur][m] = a; sv[SEG - 1 - j][m] = a;
            }
            __syncwarp();
            cur ^= 1;
        }
    } else {
        // threads 32-255 stage the x tile (coalesced LDG.128)
        const float4* xv4 = (const float4*)(x + ((size_t)(b * SEQ + g * SEG)) * DMODEL
                                              + (size_t)dt * 256);
        for (int F = tid - 32; F < SEG * 64; F += 224) {
            const int t = F >> 6, c4 = F & 63;
            ((float4*)sx)[F] = xv4[(size_t)t * (DMODEL / 4) + c4];
        }
    }
    __syncthreads();

    const int d = dt * 256 + tid;
    const ulonglong2* svp = (const ulonglong2*)sv;    // packed f32x2 pairs (broadcast)
    ull V2[8];
    #pragma unroll
    for (int j = 0; j < 8; ++j) V2[j] = 0ull;

    #pragma unroll
    for (int s = 0; s < SEG; ++s) {
        const float xv  = sx[s][tid];       // conflict-free LDS
        const ull   xv2 = pack2(xv, xv);
        const ulonglong2 p0 = svp[s * 4 + 0], p1 = svp[s * 4 + 1];
        const ulonglong2 p2 = svp[s * 4 + 2], p3 = svp[s * 4 + 3];
        fma2(V2[0], p0.x, xv2); fma2(V2[1], p0.y, xv2);
        fma2(V2[2], p1.x, xv2); fma2(V2[3], p1.y, xv2);
        fma2(V2[4], p2.x, xv2); fma2(V2[5], p2.y, xv2);
        fma2(V2[6], p3.x, xv2); fma2(V2[7], p3.y, xv2);
    }
    const int ch = b * DMODEL + d;
    ulonglong2* vp = (ulonglong2*)(g_V4 + ((size_t)g * NCH + ch) * 4);
    vp[0] = make_ulonglong2(V2[0], V2[1]);
    vp[1] = make_ulonglong2(V2[2], V2[3]);
    vp[2] = make_ulonglong2(V2[4], V2[5]);
    vp[3] = make_ulonglong2(V2[6], V2[7]);
}

// ---------------- K2: A^32 by 5 squarings in-block, then sequential prefix ----------
__global__ void __launch_bounds__(256) k2_prefix(const float* __restrict__ A) {
    __shared__ float sM[2][256];
    const int tid = threadIdx.x;
    sM[0][tid] = A[tid];
    __syncthreads();
    int cur = 0;
    const int row = tid >> 4, col = tid & 15;
    #pragma unroll
    for (int q = 0; q < 5; ++q) {               // A^(2^5) = A^32
        float a = 0.f;
        #pragma unroll
        for (int k = 0; k < NSTATE; ++k)
            a = fmaf(sM[cur][row * 16 + k], sM[cur][k * 16 + col], a);
        sM[1 - cur][tid] = a;
        __syncthreads();
        cur ^= 1;
    }

    const int m  = tid & 15;
    const int ch = (blockIdx.x * 256 + tid) >> 4;     // 256 blocks -> 4096 channels
    float ar[NSTATE];
    #pragma unroll
    for (int n = 0; n < NSTATE; ++n) ar[n] = sM[cur][m * 16 + n];

    const float* Vs = (const float*)g_V4;
    float*       Hs = (float*)g_H4;
    const size_t off0 = (size_t)ch * NSTATE + m;
    const size_t step = (size_t)NCH * NSTATE;

    float h = 0.f;
    float v = Vs[off0];                                // prefetch g=0
    size_t off = off0;
    for (int g = 0; g < NSEGS; ++g) {
        float v_next = 0.f;
        if (g < NSEGS - 1) v_next = Vs[off + step];    // prefetch next (hides L2 latency)
        Hs[off] = h;                                   // entry state of segment g
        float a0 = v, a1 = 0.f, a2 = 0.f, a3 = 0.f;
        #pragma unroll
        for (int n = 0; n < NSTATE; n += 4) {
            a0 = fmaf(ar[n + 0], __shfl_sync(0xffffffffu, h, n + 0, 16), a0);
            a1 = fmaf(ar[n + 1], __shfl_sync(0xffffffffu, h, n + 1, 16), a1);
            a2 = fmaf(ar[n + 2], __shfl_sync(0xffffffffu, h, n + 2, 16), a2);
            a3 = fmaf(ar[n + 3], __shfl_sync(0xffffffffu, h, n + 3, 16), a3);
        }
        h = (a0 + a1) + (a2 + a3);
        v = v_next;
        off += step;
    }
}

// ---------------- K3: y = conv(x) + Q . H_seg.  In-block taps; paired-f32x2 conv -----
__global__ void __launch_bounds__(256, 4) k3_fused(const float* __restrict__ x,
                                                   const float* __restrict__ A,
                                                   const float* __restrict__ bvec,
                                                   float* __restrict__ out) {
    __shared__ float sA[256];
    __shared__ float sb[NSTATE];
    __shared__ __align__(16) float sv[SEG][NSTATE];   // vrev (for c)
    __shared__ __align__(16) float sq[SEG][NSTATE];   // Q rows
    __shared__ float svc[2][NSTATE], sqc[2][NSTATE];  // chain double buffers
    __shared__ ull  cpx[SEG];                         // cpx[j] = (c[j-1] or 0, c[j])
    __shared__ __align__(16) float sx[SEG][256];      // 32 KB x tile
    const int tid = threadIdx.x;

    const int bid = blockIdx.x;             // 1024 blocks = 4 dtiles * 4 batch * 64 segs
    const int dt  = bid & 3;
    const int b   = (bid >> 2) & 3;
    const int g   = bid >> 4;
    const int d   = dt * 256 + tid;
    const int ch  = b * DMODEL + d;

    // H loads first: independent globals, in flight across chain + staging
    const float4* hp = g_H4 + ((size_t)g * NCH + ch) * 4;
    const float4 h0 = hp[0], h1 = hp[1], h2 = hp[2], h3 = hp[3];

    sA[tid] = A[tid];
    if (tid < NSTATE) {
        const float bb = bvec[tid];
        sb[tid] = bb; svc[0][tid] = bb; sqc[0][tid] = bb;
    }
    __syncthreads();

    if (tid < 32) {
        // dual chain: lanes 0-15: v <- A v (vrev); lanes 16-31: q <- A^T q (Q rows)
        const bool isV = tid < NSTATE;
        const int  m   = tid & 15;
        if (isV) sv[SEG - 1][m] = sb[m];
        int cur = 0;
        for (int j = 1; j <= SEG; ++j) {
            float a = 0.f;
            if (isV) {
                #pragma unroll
                for (int n = 0; n < NSTATE; ++n) a = fmaf(sA[m * 16 + n], svc[cur][n], a);
            } else {
                #pragma unroll
                for (int n = 0; n < NSTATE; ++n) a = fmaf(sA[n * 16 + m], sqc[cur][n], a);
            }
            if (isV) {
                if (j < SEG) { svc[1 - cur][m] = a; sv[SEG - 1 - j][m] = a; }
            } else {
                sqc[1 - cur][m] = a; sq[j - 1][m] = a;   // Q[j-1] = (A^T)^j b
            }
            __syncwarp();
            cur ^= 1;
        }
    } else {
        // threads 32-255 stage x (coalesced LDG.128) while warp 0 chains
        const float4* xv4 = (const float4*)(x + ((size_t)(b * SEQ + g * SEG)) * DMODEL
                                              + (size_t)dt * 256);
        for (int F = tid - 32; F < SEG * 64; F += 224) {
            const int t = F >> 6, c4 = F & 63;
            ((float4*)sx)[F] = xv4[(size_t)t * (DMODEL / 4) + c4];
        }
    }
    __syncthreads();

    if (tid < SEG) {    // paired tap table: cpx[j] = (c[j-1] (0 if j=0), c[j])
        float chi = 0.f, clo = 0.f;
        #pragma unroll
        for (int m = 0; m < NSTATE; ++m) chi = fmaf(sb[m], sv[SEG - 1 - tid][m], chi);
        if (tid >= 1) {
            #pragma unroll
            for (int m = 0; m < NSTATE; ++m) clo = fmaf(sb[m], sv[SEG - tid][m], clo);
        }
        cpx[tid] = pack2(clo, chi);
    }
    __syncthreads();

    ull H2[8];
    H2[0] = pack2(h0.x, h0.y); H2[1] = pack2(h0.z, h0.w);
    H2[2] = pack2(h1.x, h1.y); H2[3] = pack2(h1.z, h1.w);
    H2[4] = pack2(h2.x, h2.y); H2[5] = pack2(h2.z, h2.w);
    H2[6] = pack2(h3.x, h3.y); H2[7] = pack2(h3.z, h3.w);

    const ulonglong2* sqp = (const ulonglong2*)sq;    // Q rows as f32x2 pairs (broadcast)
    const size_t base = ((size_t)(b * SEQ + g * SEG)) * DMODEL + d;
    float* op = out + base;

    #pragma unroll
    for (int rbase = 0; rbase < SEG; rbase += 8) {
        ull acc2[4];                        // 4 output pairs (r, r+1)
        #pragma unroll
        for (int i = 0; i < 4; ++i) {       // init with Q[r] . H
            float qh[2];
            #pragma unroll
            for (int hh = 0; hh < 2; ++hh) {
                const int r = rbase + 2 * i + hh;
                const ulonglong2 qa = sqp[r * 4 + 0], qb = sqp[r * 4 + 1];
                const ulonglong2 qc = sqp[r * 4 + 2], qd = sqp[r * 4 + 3];
                ull p = 0ull;
                fma2(p, qa.x, H2[0]); fma2(p, qa.y, H2[1]);
                fma2(p, qb.x, H2[2]); fma2(p, qb.y, H2[3]);
                fma2(p, qc.x, H2[4]); fma2(p, qc.y, H2[5]);
                fma2(p, qd.x, H2[6]); fma2(p, qd.y, H2[7]);
                qh[hh] = unpack_add(p);
            }
            acc2[i] = pack2(qh[0], qh[1]);
        }
        // conv, outputs paired: acc2[i] += (c[r-s], c[r+1-s]) * (xv, xv)
        #pragma unroll
        for (int s = 0; s < SEG; ++s) {
            if (s > rbase + 7) break;
            const float xv  = sx[s][tid];
            const ull   xv2 = pack2(xv, xv);
            #pragma unroll
            for (int i = 0; i < 4; ++i) {
                const int j = rbase + 2 * i - s + 1;   // compile-time
                if (j >= 0) fma2(acc2[i], cpx[j], xv2);  // j <= 31 always
            }
        }
        #pragma unroll
        for (int i = 0; i < 4; ++i) {
            float lo, hi; unpack2(lo, hi, acc2[i]);
            op[(size_t)(rbase + 2 * i)     * DMODEL] = lo;
            op[(size_t)(rbase + 2 * i + 1) * DMODEL] = hi;
        }
    }
}

// ---------------- launch ----------------
extern "C" void kernel_launch(void* const* d_in, const int* in_sizes, int n_in,
                              void* d_out, int out_size) {
    const float* x = nullptr; const float* A = nullptr; const float* bv = nullptr;
    for (int i = 0; i < n_in; ++i) {
        if      (in_sizes[i] == BATCH * SEQ * DMODEL) x  = (const float*)d_in[i];
        else if (in_sizes[i] == NSTATE * NSTATE)      A  = (const float*)d_in[i];
        else if (in_sizes[i] == NSTATE)               bv = (const float*)d_in[i];
    }
    float* out = (float*)d_out;

    k1_inject<<<(NCH * NSEGS) / 256, 256>>>(x, A, bv);       // 1024 blocks
    k2_prefix<<<(NCH * NSTATE) / 256, 256>>>(A);             // 256 blocks
    k3_fused<<<(NCH * NSEGS) / 256, 256>>>(x, A, bv, out);   // 1024 blocks
}

// round 17
// speedup vs baseline: 1.4721x; 1.4721x over previous
#include <cuda_runtime.h>
#include <cuda_bf16.h>

#define BATCH  4
#define SEQ    2048
#define DMODEL 1024
#define NSTATE 16
#define SEG    32                  // segment length
#define NSEGS  (SEQ / SEG)         // 64 segments
#define NCH    (BATCH * DMODEL)    // 4096 channels

typedef unsigned long long ull;

// packed f32x2 helpers (true fp32 lanes — no precision loss)
__device__ __forceinline__ ull pack2(float lo, float hi) {
    ull r; asm("mov.b64 %0, {%1, %2};" : "=l"(r) : "f"(lo), "f"(hi)); return r;
}
__device__ __forceinline__ void fma2(ull& d, ull a, ull b) {
    asm("fma.rn.f32x2 %0, %1, %2, %0;" : "+l"(d) : "l"(a), "l"(b));
}
__device__ __forceinline__ float unpack_add(ull p) {
    float lo, hi; asm("mov.b64 {%0, %1}, %2;" : "=f"(lo), "=f"(hi) : "l"(p));
    return lo + hi;
}

// ---------------- device scratch (static: no allocation) ----------------
__device__ float  g_c[SEG];                   // c_k = b^T A^k b
__device__ float4 g_vrev4[SEG][4];            // vrev[s] = A^{SEG-1-s} b   (float4-packed)
__device__ float4 g_Q4[SEG][4];               // Q[r]  = b^T A^{r+1}      (float4-packed)
__device__ float  g_A32[NSTATE * NSTATE];     // A^SEG
__device__ float4 g_V4[NSEGS * NCH * 4];      // injected state  [g][ch][16]   (16.8 MB)
__device__ float4 g_H4[NSEGS * NCH * 4];      // entry states    [g][ch][16]   (16.8 MB)

// ---------------- K0: precompute filter taps and transition powers (R5 exact) -------
__global__ void __launch_bounds__(256) k0_precompute(const float* __restrict__ A,
                                                     const float* __restrict__ bvec) {
    __shared__ float sA[NSTATE * NSTATE];
    __shared__ float M[2][NSTATE * NSTATE];
    __shared__ float sb[NSTATE];
    const int tid = threadIdx.x;            // 256 threads
    sA[tid] = A[tid];
    if (tid < NSTATE) sb[tid] = bvec[tid];
    M[0][tid] = ((tid >> 4) == (tid & 15)) ? 1.f : 0.f;   // M = I
    __syncthreads();

    float* vrev = (float*)g_vrev4;
    float* Q    = (float*)g_Q4;

    int cur = 0;
    const int row = tid >> 4, col = tid & 15;
    for (int j = 0; j < SEG; ++j) {         // at loop top: M[cur] = A^j
        if (tid < NSTATE) {                 // vrev[SEG-1-j] = A^j b
            float a = 0.f;
            #pragma unroll
            for (int n = 0; n < NSTATE; ++n) a = fmaf(M[cur][tid * NSTATE + n], sb[n], a);
            vrev[(SEG - 1 - j) * NSTATE + tid] = a;
        } else if (tid < 32 && j >= 1) {    // Q[j-1] = b^T A^j
            const int m = tid - NSTATE;
            float a = 0.f;
            #pragma unroll
            for (int k = 0; k < NSTATE; ++k) a = fmaf(sb[k], M[cur][k * NSTATE + m], a);
            Q[(j - 1) * NSTATE + m] = a;
        }
        float a = 0.f;                      // M[1-cur] = M[cur] * A
        #pragma unroll
        for (int k = 0; k < NSTATE; ++k)
            a = fmaf(M[cur][row * NSTATE + k], sA[k * NSTATE + col], a);
        M[1 - cur][tid] = a;
        __syncthreads();
        cur ^= 1;
    }
    // M[cur] = A^SEG
    g_A32[tid] = M[cur][tid];
    if (tid < NSTATE) {                     // Q[SEG-1] = b^T A^SEG
        float a = 0.f;
        #pragma unroll
        for (int k = 0; k < NSTATE; ++k) a = fmaf(sb[k], M[cur][k * NSTATE + tid], a);
        Q[(SEG - 1) * NSTATE + tid] = a;
    }
    if (tid < SEG) {                        // c_k = b . A^k b
        float a = 0.f;
        #pragma unroll
        for (int m = 0; m < NSTATE; ++m) a = fmaf(sb[m], vrev[(SEG - 1 - tid) * NSTATE + m], a);
        g_c[tid] = a;
    }
}

// ---------------- K1: injected state V = sum_s A^{SEG-1-s} b x_s  (R5 exact) --------
// Plain scalar FMA version, no reg cap: from the 70.1us build. Every "improved" k1
// (f32x2, staging, reg caps, in-block chains) measured slower in totals — keep this.
__global__ void __launch_bounds__(256) k1_inject(const float* __restrict__ x) {
    __shared__ float4 sv4[SEG][4];
    const int tid = threadIdx.x;
    if (tid < SEG * 4) ((float4*)sv4)[tid] = ((const float4*)g_vrev4)[tid];
    __syncthreads();

    const int job = blockIdx.x * 256 + tid;     // 262144 jobs = (ch, seg)
    const int d = job & (DMODEL - 1);
    const int b = (job >> 10) & 3;
    const int g = job >> 12;

    const float* xp = x + ((size_t)(b * SEQ + g * SEG)) * DMODEL + d;
    float V[NSTATE];
    #pragma unroll
    for (int m = 0; m < NSTATE; ++m) V[m] = 0.f;

    #pragma unroll
    for (int s = 0; s < SEG; ++s) {
        const float xv = xp[(size_t)s * DMODEL];
        const float4 a0 = sv4[s][0], a1 = sv4[s][1], a2 = sv4[s][2], a3 = sv4[s][3];
        V[0]  = fmaf(a0.x, xv, V[0]);  V[1]  = fmaf(a0.y, xv, V[1]);
        V[2]  = fmaf(a0.z, xv, V[2]);  V[3]  = fmaf(a0.w, xv, V[3]);
        V[4]  = fmaf(a1.x, xv, V[4]);  V[5]  = fmaf(a1.y, xv, V[5]);
        V[6]  = fmaf(a1.z, xv, V[6]);  V[7]  = fmaf(a1.w, xv, V[7]);
        V[8]  = fmaf(a2.x, xv, V[8]);  V[9]  = fmaf(a2.y, xv, V[9]);
        V[10] = fmaf(a2.z, xv, V[10]); V[11] = fmaf(a2.w, xv, V[11]);
        V[12] = fmaf(a3.x, xv, V[12]); V[13] = fmaf(a3.y, xv, V[13]);
        V[14] = fmaf(a3.z, xv, V[14]); V[15] = fmaf(a3.w, xv, V[15]);
    }
    const int ch = b * DMODEL + d;
    float4* vp = g_V4 + ((size_t)g * NCH + ch) * 4;
    vp[0] = make_float4(V[0],  V[1],  V[2],  V[3]);
    vp[1] = make_float4(V[4],  V[5],  V[6],  V[7]);
    vp[2] = make_float4(V[8],  V[9],  V[10], V[11]);
    vp[3] = make_float4(V[12], V[13], V[14], V[15]);
}

// ---------------- K2: fused sequential prefix over segments (R12 exact) -------------
__global__ void __launch_bounds__(256) k2_prefix(void) {
    const int tid = threadIdx.x;
    const int m   = tid & 15;
    const int ch  = (blockIdx.x * 256 + tid) >> 4;     // 256 blocks -> 4096 channels

    float ar[NSTATE];
    #pragma unroll
    for (int n = 0; n < NSTATE; ++n) ar[n] = g_A32[m * NSTATE + n];

    const float* Vs = (const float*)g_V4;
    float*       Hs = (float*)g_H4;
    const size_t off0 = (size_t)ch * NSTATE + m;
    const size_t step = (size_t)NCH * NSTATE;

    float h = 0.f;
    float v = Vs[off0];                                // prefetch g=0
    size_t off = off0;
    for (int g = 0; g < NSEGS; ++g) {
        float v_next = 0.f;
        if (g < NSEGS - 1) v_next = Vs[off + step];    // prefetch next (hides L2 latency)
        Hs[off] = h;                                   // entry state of segment g
        float a0 = v, a1 = 0.f, a2 = 0.f, a3 = 0.f;
        #pragma unroll
        for (int n = 0; n < NSTATE; n += 4) {
            a0 = fmaf(ar[n + 0], __shfl_sync(0xffffffffu, h, n + 0, 16), a0);
            a1 = fmaf(ar[n + 1], __shfl_sync(0xffffffffu, h, n + 1, 16), a1);
            a2 = fmaf(ar[n + 2], __shfl_sync(0xffffffffu, h, n + 2, 16), a2);
            a3 = fmaf(ar[n + 3], __shfl_sync(0xffffffffu, h, n + 3, 16), a3);
        }
        h = (a0 + a1) + (a2 + a3);
        v = v_next;
        off += step;
    }
}

// ---------------- K3: y = conv(x) + Q . H_seg  (R12 exact: 23.4us measured twice) ---
__global__ void __launch_bounds__(256, 4) k3_fused(const float* __restrict__ x,
                                                   float* __restrict__ out) {
    __shared__ float      sx[SEG][256];     // 32 KB x tile, read once from DRAM
    __shared__ float      sc[SEG];
    __shared__ ulonglong2 sQp[SEG][4];      // Q rows as packed f32x2 pairs
    const int tid = threadIdx.x;
    if (tid < SEG) sc[tid] = g_c[tid];
    if (tid < SEG * 4) ((ulonglong2*)sQp)[tid] = ((const ulonglong2*)g_Q4)[tid];

    const int bid = blockIdx.x;             // 1024 blocks = 4 dtiles * 4 batch * 64 segs
    const int dt  = bid & 3;
    const int b   = (bid >> 2) & 3;
    const int g   = bid >> 4;
    const int d   = dt * 256 + tid;
    const int ch  = b * DMODEL + d;

    // H loads issued first: in flight across staging + syncthreads
    const float4* hp = g_H4 + ((size_t)g * NCH + ch) * 4;
    const float4 h0 = hp[0], h1 = hp[1], h2 = hp[2], h3 = hp[3];

    const size_t base = ((size_t)(b * SEQ + g * SEG)) * DMODEL + d;
    const float* xp = x + base;
    #pragma unroll
    for (int s = 0; s < SEG; ++s) sx[s][tid] = xp[(size_t)s * DMODEL];
    __syncthreads();

    ull H2[8];
    H2[0] = pack2(h0.x, h0.y); H2[1] = pack2(h0.z, h0.w);
    H2[2] = pack2(h1.x, h1.y); H2[3] = pack2(h1.z, h1.w);
    H2[4] = pack2(h2.x, h2.y); H2[5] = pack2(h2.z, h2.w);
    H2[6] = pack2(h3.x, h3.y); H2[7] = pack2(h3.z, h3.w);

    float* op = out + base;

    #pragma unroll
    for (int rbase = 0; rbase < SEG; rbase += 8) {
        float acc[8];
        // acc[i] = Q[rbase+i] . H   (packed: 8 fma2 per output)
        #pragma unroll
        for (int i = 0; i < 8; ++i) {
            const ulonglong2 qa = sQp[rbase + i][0], qb = sQp[rbase + i][1];
            const ulonglong2 qc = sQp[rbase + i][2], qd = sQp[rbase + i][3];
            ull p = 0ull;
            fma2(p, qa.x, H2[0]); fma2(p, qa.y, H2[1]);
            fma2(p, qb.x, H2[2]); fma2(p, qb.y, H2[3]);
            fma2(p, qc.x, H2[4]); fma2(p, qc.y, H2[5]);
            fma2(p, qd.x, H2[6]); fma2(p, qd.y, H2[7]);
            acc[i] = unpack_add(p);
        }
        // conv: acc[i] += sum_s c[rbase+i-s] * x[s]; compile-time predicates only
        #pragma unroll
        for (int s = 0; s < SEG; ++s) {
            if (s > rbase + 7) break;
            const float xv = sx[s][tid];
            #pragma unroll
            for (int i = 0; i < 8; ++i) {
                const int k = rbase + i - s;
                if (k >= 0 && k < SEG) acc[i] = fmaf(sc[k], xv, acc[i]);
            }
        }
        #pragma unroll
        for (int i = 0; i < 8; ++i) op[(size_t)(rbase + i) * DMODEL] = acc[i];
    }
}

// ---------------- launch ----------------
extern "C" void kernel_launch(void* const* d_in, const int* in_sizes, int n_in,
                              void* d_out, int out_size) {
    const float* x = nullptr; const float* A = nullptr; const float* bv = nullptr;
    for (int i = 0; i < n_in; ++i) {
        if      (in_sizes[i] == BATCH * SEQ * DMODEL) x  = (const float*)d_in[i];
        else if (in_sizes[i] == NSTATE * NSTATE)      A  = (const float*)d_in[i];
        else if (in_sizes[i] == NSTATE)               bv = (const float*)d_in[i];
    }
    float* out = (float*)d_out;

    k0_precompute<<<1, 256>>>(A, bv);
    k1_inject<<<(NCH * NSEGS) / 256, 256>>>(x);              // 1024 blocks
    k2_prefix<<<(NCH * NSTATE) / 256, 256>>>();              // 256 blocks
    k3_fused<<<(NCH * NSEGS) / 256, 256>>>(x, out);          // 1024 blocks
}